// round 14
// baseline (speedup 1.0000x reference)
#include <cuda_runtime.h>
#include <cuda_fp16.h>
#include <cstdint>

#define TPB    128
#define NSTEPS 254

// ---- strides (bytes) ----
#define XSB   272            // activation row stride (136 halfs, 17x16B -> conflict-free ldmatrix)
#define W1SB  80             // W1 row stride (40 halfs, 5x16B)
#define WSB   272            // W2/W3 row stride

// ---- smem byte offsets ----
#define OFF_W1    0          // [128][40]  half   10240
#define OFF_W2    10240      // [128][136] half   34816
#define OFF_W3    45056      // [256][136] half   69632
#define OFF_XACT  114688     // [128][136] half   34816
#define OFF_AC    149504     // f32 [128][33]     16896
#define OFF_DB    166400     // f32 [128][33]     16896
#define OFF_KB    183296     // f32 [128][33]     16896
#define OFF_DX    200192     // f32 [128][8]       4096
#define OFF_RW    204288     // f32 readout        4356
#define SMEM_TOTAL 208896

#define RW1 0
#define RB1 1024
#define RW2 1056
#define RB2 1088

// ---------------- helpers ----------------
static __device__ __forceinline__ uint32_t smem_u32(const void* p) {
    uint32_t a;
    asm("{ .reg .u64 t; cvta.to.shared.u64 t, %1; cvt.u32.u64 %0, t; }" : "=r"(a) : "l"(p));
    return a;
}
// accurate tanh: 2 MUFU (ex2, rcp) + fma; ~1e-6 error, correct saturation
static __device__ __forceinline__ float tanh_acc(float x) {
    float e = __expf(2.0f * x);
    return 1.0f - 2.0f / (e + 1.0f);
}
static __device__ __forceinline__ void ldsm4(uint32_t addr, uint32_t& r0, uint32_t& r1,
                                             uint32_t& r2, uint32_t& r3) {
    asm volatile("ldmatrix.sync.aligned.m8n8.x4.shared.b16 {%0,%1,%2,%3}, [%4];"
        : "=r"(r0), "=r"(r1), "=r"(r2), "=r"(r3) : "r"(addr));
}
static __device__ __forceinline__ void ldsm2(uint32_t addr, uint32_t& r0, uint32_t& r1) {
    asm volatile("ldmatrix.sync.aligned.m8n8.x2.shared.b16 {%0,%1}, [%2];"
        : "=r"(r0), "=r"(r1) : "r"(addr));
}
static __device__ __forceinline__ void mma16(float* c, const uint32_t* a, uint32_t b0, uint32_t b1) {
    asm volatile("mma.sync.aligned.m16n8k16.row.col.f32.f16.f16.f32 "
        "{%0,%1,%2,%3},{%4,%5,%6,%7},{%8,%9},{%0,%1,%2,%3};"
        : "+f"(c[0]), "+f"(c[1]), "+f"(c[2]), "+f"(c[3])
        : "r"(a[0]), "r"(a[1]), "r"(a[2]), "r"(a[3]), "r"(b0), "r"(b1));
}
static __device__ __forceinline__ void mma8(float* c, const uint32_t* a, uint32_t b0) {
    asm volatile("mma.sync.aligned.m16n8k8.row.col.f32.f16.f16.f32 "
        "{%0,%1,%2,%3},{%4,%5},{%6},{%0,%1,%2,%3};"
        : "+f"(c[0]), "+f"(c[1]), "+f"(c[2]), "+f"(c[3])
        : "r"(a[0]), "r"(a[1]), "r"(b0));
}

// ---------------- one layer GEMM for this warp ----------------
// A rows [m0, m0+32) from Xact (K = 16*KST + 8, tail at k=16*KST).
// W at wbase with row stride WSBI. N processed in NCH chunks of 64.
// EPI 0: tanh -> Xact cols [n].  EPI 1: k-epilogue (tanh * dx, c-reduce -> KB).
template<int KST, int NCH, int EPI, int WSBI>
static __device__ __forceinline__ void gemm_layer(
    char* sm, uint32_t smb, uint32_t wbase, int m0, int lane)
{
    const uint32_t XB = smb + OFF_XACT;
    const int ar = (lane & 7) + ((lane >> 3) & 1) * 8;   // A x4 row offset
    const int ak = ((lane >> 4) & 1) * 8;                // A x4 k offset
    const int br = (lane & 7) + ((lane >> 4) & 1) * 8;   // B x4 row offset
    const int bk = ((lane >> 3) & 1) * 8;                // B x4 k offset
    const int rr = lane & 15;                            // x2 row offset

    // ---- hoist ALL A fragments (before epilogue overwrites Xact in place) ----
    uint32_t AF[KST][2][4];
    uint32_t AT[2][2];
#pragma unroll
    for (int ks = 0; ks < KST; ks++)
#pragma unroll
        for (int mt = 0; mt < 2; mt++)
            ldsm4(XB + (uint32_t)(m0 + mt * 16 + ar) * XSB + (uint32_t)(ks * 16 + ak) * 2,
                  AF[ks][mt][0], AF[ks][mt][1], AF[ks][mt][2], AF[ks][mt][3]);
#pragma unroll
    for (int mt = 0; mt < 2; mt++)
        ldsm2(XB + (uint32_t)(m0 + mt * 16 + rr) * XSB + (uint32_t)(KST * 16) * 2,
              AT[mt][0], AT[mt][1]);

    const int g  = lane >> 2;
    const int q2 = (lane & 3) * 2;

#pragma unroll
    for (int ch = 0; ch < NCH; ch++) {
        const int n0 = ch * 64;
        float acc[2][8][4];
#pragma unroll
        for (int mt = 0; mt < 2; mt++)
#pragma unroll
            for (int nt = 0; nt < 8; nt++)
#pragma unroll
                for (int j = 0; j < 4; j++) acc[mt][nt][j] = 0.0f;

#pragma unroll
        for (int ks = 0; ks < KST; ks++) {
#pragma unroll
            for (int np = 0; np < 4; np++) {
                uint32_t b0, b1, b2, b3;
                ldsm4(wbase + (uint32_t)(n0 + np * 16 + br) * WSBI + (uint32_t)(ks * 16 + bk) * 2,
                      b0, b1, b2, b3);
                mma16(acc[0][2 * np],     AF[ks][0], b0, b1);
                mma16(acc[0][2 * np + 1], AF[ks][0], b2, b3);
                mma16(acc[1][2 * np],     AF[ks][1], b0, b1);
                mma16(acc[1][2 * np + 1], AF[ks][1], b2, b3);
            }
        }
        { // K tail (k8)
#pragma unroll
            for (int np = 0; np < 4; np++) {
                uint32_t b0, b1;
                ldsm2(wbase + (uint32_t)(n0 + np * 16 + rr) * WSBI + (uint32_t)(KST * 16) * 2,
                      b0, b1);
                mma8(acc[0][2 * np],     AT[0], b0);
                mma8(acc[0][2 * np + 1], AT[0], b1);
                mma8(acc[1][2 * np],     AT[1], b0);
                mma8(acc[1][2 * np + 1], AT[1], b1);
            }
        }

        if (EPI == 0) {
            // tanh -> Xact (fp16) at cols n0..n0+63
#pragma unroll
            for (int mt = 0; mt < 2; mt++) {
                int rowA = m0 + mt * 16 + g;
#pragma unroll
                for (int nt = 0; nt < 8; nt++) {
                    int col = n0 + nt * 8 + q2;
                    __half2 lo = __floats2half2_rn(tanh_acc(acc[mt][nt][0]),
                                                   tanh_acc(acc[mt][nt][1]));
                    __half2 hi = __floats2half2_rn(tanh_acc(acc[mt][nt][2]),
                                                   tanh_acc(acc[mt][nt][3]));
                    *(__half2*)(sm + OFF_XACT + (size_t)rowA * XSB + col * 2)       = lo;
                    *(__half2*)(sm + OFF_XACT + (size_t)(rowA + 8) * XSB + col * 2) = hi;
                }
            }
        } else {
            // k-epilogue: k[row][h] = sum_c tanh(D)*dx[row][c]
            const float* dxs = (const float*)(sm + OFF_DX);
            float* kb = (float*)(sm + OFF_KB);
#pragma unroll
            for (int mt = 0; mt < 2; mt++) {
                int rA = m0 + mt * 16 + g, rB = rA + 8;
                float2 dA = *(const float2*)(dxs + rA * 8 + q2);
                float2 dB = *(const float2*)(dxs + rB * 8 + q2);
#pragma unroll
                for (int nt = 0; nt < 8; nt++) {
                    int h = (n0 >> 3) + nt;
                    float pA = tanh_acc(acc[mt][nt][0]) * dA.x + tanh_acc(acc[mt][nt][1]) * dA.y;
                    float pB = tanh_acc(acc[mt][nt][2]) * dB.x + tanh_acc(acc[mt][nt][3]) * dB.y;
                    pA += __shfl_xor_sync(0xFFFFFFFFu, pA, 1);
                    pA += __shfl_xor_sync(0xFFFFFFFFu, pA, 2);
                    pB += __shfl_xor_sync(0xFFFFFFFFu, pB, 1);
                    pB += __shfl_xor_sync(0xFFFFFFFFu, pB, 2);
                    if ((lane & 3) == 0) {
                        kb[rA * 33 + h] = pA;
                        kb[rB * 33 + h] = pB;
                    }
                }
            }
        }
    }
}

// ---------------- kernel ----------------
__global__ void __launch_bounds__(TPB, 1) cde_kernel(
    const float* __restrict__ coeffs,
    const float* __restrict__ iW1, const float* __restrict__ ib1,
    const float* __restrict__ iW2, const float* __restrict__ ib2,
    const float* __restrict__ fW1, const float* __restrict__ fb1,
    const float* __restrict__ fW2, const float* __restrict__ fb2,
    const float* __restrict__ fW3, const float* __restrict__ fb3,
    const float* __restrict__ rW1, const float* __restrict__ rb1,
    const float* __restrict__ rW2, const float* __restrict__ rb2,
    float* __restrict__ out)
{
    extern __shared__ char sm[];
    const uint32_t smb = smem_u32(sm);
    const int tid  = threadIdx.x;
    const int lane = tid & 31;
    const int m0   = (tid >> 5) * 32;                    // warp's M base
    const size_t b = (size_t)blockIdx.x * TPB + tid;     // batch row owned by this thread

    // ========== weight staging: fp16 [N][K] row-major, bias folded at k=K_real ==========
    // W1: K=40 (32 data + bias@32 + zeros)
    for (int e = tid; e < 128 * 40; e += TPB) {
        int n = e / 40, k = e % 40;
        float v = (k < 32) ? fW1[k * 128 + n] : (k == 32 ? fb1[n] : 0.0f);
        *(__half*)(sm + OFF_W1 + (size_t)n * W1SB + k * 2) = __float2half_rn(v);
    }
    // W2: K=136 (128 data + bias@128 + zeros)
    for (int e = tid; e < 128 * 136; e += TPB) {
        int n = e / 136, k = e % 136;
        float v = (k < 128) ? fW2[k * 128 + n] : (k == 128 ? fb2[n] : 0.0f);
        *(__half*)(sm + OFF_W2 + (size_t)n * WSB + k * 2) = __float2half_rn(v);
    }
    // W3: 256 output cols
    for (int e = tid; e < 256 * 136; e += TPB) {
        int n = e / 136, k = e % 136;
        float v = (k < 128) ? fW3[k * 256 + n] : (k == 128 ? fb3[n] : 0.0f);
        *(__half*)(sm + OFF_W3 + (size_t)n * WSB + k * 2) = __float2half_rn(v);
    }
    // readout weights -> smem
    {
        float* rw = (float*)(sm + OFF_RW);
        for (int i = tid; i < 1024; i += TPB) rw[RW1 + i] = rW1[i];
        if (tid < 32) { rw[RB1 + tid] = rb1[tid]; rw[RW2 + tid] = rW2[tid]; }
        if (tid == 0) rw[RB2] = rb2[0];
    }

    // ========== z0 = initial(X(0)) (one-time, weights straight from global/L2) ==========
    const float* base_c = coeffs + b * (size_t)(127 * 32);
    float z[32];
    {
        float X0[8];
        float4 q0 = *(const float4*)(base_c + 0);
        float4 q1 = *(const float4*)(base_c + 4);
        X0[0]=q0.x; X0[1]=q0.y; X0[2]=q0.z; X0[3]=q0.w;
        X0[4]=q1.x; X0[5]=q1.y; X0[6]=q1.z; X0[7]=q1.w;
#pragma unroll
        for (int i = 0; i < 32; i++) z[i] = ib2[i];
        for (int j = 0; j < 64; j++) {
            float hj = ib1[j];
#pragma unroll
            for (int c = 0; c < 8; c++) hj += X0[c] * iW1[c * 64 + j];
            hj = fmaxf(hj, 0.0f);
#pragma unroll
            for (int i = 0; i < 32; i++) z[i] += hj * iW2[j * 32 + i];
        }
    }

    // ========== initial Xact row: arg = z, bias cols ==========
    __half2* xr = (__half2*)(sm + OFF_XACT + (size_t)tid * XSB);
#pragma unroll
    for (int i = 0; i < 16; i++) xr[i] = __floats2half2_rn(z[2 * i], z[2 * i + 1]);
    xr[16] = __floats2half2_rn(1.0f, 0.0f);              // bias col 32 (layer1)
    xr[17] = xr[18] = xr[19] = __floats2half2_rn(0.0f, 0.0f);
    xr[64] = __floats2half2_rn(1.0f, 0.0f);              // bias col 128 (layer2/3)
    xr[65] = xr[66] = xr[67] = __floats2half2_rn(0.0f, 0.0f);

    __syncthreads();   // weights + activations visible CTA-wide (one-time)

    // ---- knot 0 ----
    {
        const float* rw = (const float*)(sm + OFF_RW);
        float h[32];
#pragma unroll
        for (int j = 0; j < 32; j++) h[j] = rw[RB1 + j];
#pragma unroll
        for (int i = 0; i < 32; i++) {
            float zi = z[i];
#pragma unroll
            for (int j = 0; j < 32; j++) h[j] += zi * rw[RW1 + i * 32 + j];
        }
        float y = rw[RB2];
#pragma unroll
        for (int j = 0; j < 32; j++) y += fmaxf(h[j], 0.0f) * rw[RW2 + j];
        out[b * 128] = y;
    }

    // ========== RK4 (3/8 rule) main loop — warp-autonomous, no __syncthreads ==========
    float* acp = (float*)(sm + OFF_AC) + tid * 33;
    float* dbp = (float*)(sm + OFF_DB) + tid * 33;
    float* kbp = (float*)(sm + OFF_KB) + tid * 33;
    float* dxp = (float*)(sm + OFF_DX) + tid * 8;

    int cur = -1;
    float cb[8], c2r[8], c3r[8];

#pragma unroll 1
    for (int step = 0; step < NSTEPS; step++) {
        const float t0 = 0.5f * (float)step;
#pragma unroll 1
        for (int s = 0; s < 4; s++) {
            float ts = t0 + (s == 0 ? 0.0f : s == 1 ? 0.16666667f
                                           : s == 2 ? 0.33333334f : 0.5f);
            // ---- dx(ts) for own row -> smem ----
            {
                int id = (int)ts; if (id > 126) id = 126;
                float fr = ts - (float)id;
                if (id != cur) {
                    cur = id;
                    const float4* cp = (const float4*)(base_c + (size_t)id * 32);
                    float4 q;
                    q = cp[2]; cb[0]=q.x;  cb[1]=q.y;  cb[2]=q.z;  cb[3]=q.w;
                    q = cp[3]; cb[4]=q.x;  cb[5]=q.y;  cb[6]=q.z;  cb[7]=q.w;
                    q = cp[4]; c2r[0]=q.x; c2r[1]=q.y; c2r[2]=q.z; c2r[3]=q.w;
                    q = cp[5]; c2r[4]=q.x; c2r[5]=q.y; c2r[6]=q.z; c2r[7]=q.w;
                    q = cp[6]; c3r[0]=q.x; c3r[1]=q.y; c3r[2]=q.z; c3r[3]=q.w;
                    q = cp[7]; c3r[4]=q.x; c3r[5]=q.y; c3r[6]=q.z; c3r[7]=q.w;
                }
#pragma unroll
                for (int c = 0; c < 8; c++)
                    dxp[c] = cb[c] + (c2r[c] + c3r[c] * fr) * fr;
            }
            __syncwarp();

            // ---- 3-layer MLP: arg in Xact -> k in KB ----
            gemm_layer<2, 2, 0, W1SB>(sm, smb, smb + OFF_W1, m0, lane);
            __syncwarp();
            gemm_layer<8, 2, 0, WSB>(sm, smb, smb + OFF_W2, m0, lane);
            __syncwarp();
            gemm_layer<8, 4, 1, WSB>(sm, smb, smb + OFF_W3, m0, lane);
            __syncwarp();

            // ---- RK4 combination (thread = own row), write next arg ----
#pragma unroll
            for (int i = 0; i < 32; i += 2) {
                float k0 = kbp[i], k1 = kbp[i + 1];
                float v0, v1;
                if (s == 0) {
                    acp[i] = k0; acp[i + 1] = k1;
                    dbp[i] = k0; dbp[i + 1] = k1;
                    v0 = z[i]     + k0 * (1.0f / 6.0f);
                    v1 = z[i + 1] + k1 * (1.0f / 6.0f);
                } else if (s == 1) {
                    float a0 = acp[i] + 3.0f * k0, a1 = acp[i + 1] + 3.0f * k1;
                    float d0 = dbp[i] - k0,        d1 = dbp[i + 1] - k1;
                    acp[i] = a0; acp[i + 1] = a1;
                    dbp[i] = d0; dbp[i + 1] = d1;
                    v0 = z[i]     + (a0 - 3.0f * d0) * (1.0f / 12.0f);
                    v1 = z[i + 1] + (a1 - 3.0f * d1) * (1.0f / 12.0f);
                } else if (s == 2) {
                    float a0 = acp[i] + 3.0f * k0, a1 = acp[i + 1] + 3.0f * k1;
                    float d0 = dbp[i] + k0,        d1 = dbp[i + 1] + k1;
                    acp[i] = a0; acp[i + 1] = a1;
                    dbp[i] = d0; dbp[i + 1] = d1;
                    v0 = z[i]     + 0.5f * d0;
                    v1 = z[i + 1] + 0.5f * d1;
                } else {
                    z[i]     += 0.0625f * (acp[i]     + k0);
                    z[i + 1] += 0.0625f * (acp[i + 1] + k1);
                    v0 = z[i]; v1 = z[i + 1];
                }
                xr[i >> 1] = __floats2half2_rn(v0, v1);
            }
            // restore layer-1 bias/zero cols (clobbered by layer-1 epilogue)
            xr[16] = __floats2half2_rn(1.0f, 0.0f);
            xr[17] = xr[18] = xr[19] = __floats2half2_rn(0.0f, 0.0f);
            __syncwarp();
        }

        // ---- readout at integer knots ----
        if (step & 1) {
            const float* rw = (const float*)(sm + OFF_RW);
            float h[32];
#pragma unroll
            for (int j = 0; j < 32; j++) h[j] = rw[RB1 + j];
#pragma unroll
            for (int i = 0; i < 32; i++) {
                float zi = z[i];
#pragma unroll
                for (int j = 0; j < 32; j++) h[j] += zi * rw[RW1 + i * 32 + j];
            }
            float y = rw[RB2];
#pragma unroll
            for (int j = 0; j < 32; j++) y += fmaxf(h[j], 0.0f) * rw[RW2 + j];
            out[b * 128 + (size_t)((step >> 1) + 1)] = y;
        }
    }
}

extern "C" void kernel_launch(void* const* d_in, const int* in_sizes, int n_in,
                              void* d_out, int out_size)
{
    (void)in_sizes; (void)n_in; (void)out_size;
    cudaFuncSetAttribute(cde_kernel, cudaFuncAttributeMaxDynamicSharedMemorySize, SMEM_TOTAL);
    cde_kernel<<<128, TPB, SMEM_TOTAL>>>(
        (const float*)d_in[0],                              // coeffs (d_in[1]=t_eval unused)
        (const float*)d_in[2],  (const float*)d_in[3],      // iW1, ib1
        (const float*)d_in[4],  (const float*)d_in[5],      // iW2, ib2
        (const float*)d_in[6],  (const float*)d_in[7],      // fW1, fb1
        (const float*)d_in[8],  (const float*)d_in[9],      // fW2, fb2
        (const float*)d_in[10], (const float*)d_in[11],     // fW3, fb3
        (const float*)d_in[12], (const float*)d_in[13],     // rW1, rb1
        (const float*)d_in[14], (const float*)d_in[15],     // rW2, rb2
        (float*)d_out);
}

// round 15
// speedup vs baseline: 8.7756x; 8.7756x over previous
#include <cuda_runtime.h>
#include <cuda_fp16.h>
#include <cstdint>

#define TPB    256           // 8 warps: warp w owns rows 16w..16w+15 (M=16)
#define ROWS   128           // batch rows per CTA
#define NSTEPS 254

// ---- strides (bytes) ----
#define XSB   272            // activation row stride (136 halfs, 17x16B -> conflict-free ldmatrix)
#define W1SB  80             // W1 row stride (40 halfs, 5x16B)
#define WSB   272            // W2/W3 row stride

// ---- smem byte offsets ----
#define OFF_W1    0          // [128][40]  half   10240
#define OFF_W2    10240      // [128][136] half   34816
#define OFF_W3    45056      // [256][136] half   69632
#define OFF_XACT  114688     // [128][136] half   34816
#define OFF_AC    149504     // f32 [128][33]     16896
#define OFF_DB    166400     // f32 [128][33]     16896
#define OFF_KB    183296     // f32 [128][33]     16896
#define OFF_DX    200192     // f32 [128][8]       4096
#define OFF_RW    204288     // f32 readout        4356
#define SMEM_TOTAL 208896

#define RW1 0
#define RB1 1024
#define RW2 1056
#define RB2 1088

// ---------------- helpers ----------------
static __device__ __forceinline__ uint32_t smem_u32(const void* p) {
    uint32_t a;
    asm("{ .reg .u64 t; cvta.to.shared.u64 t, %1; cvt.u32.u64 %0, t; }" : "=r"(a) : "l"(p));
    return a;
}
// HW tanh approximation: 1 MUFU op, ~5e-4 abs error, correct saturation
static __device__ __forceinline__ float tanh_fast(float x) {
    float y; asm("tanh.approx.f32 %0, %1;" : "=f"(y) : "f"(x)); return y;
}
static __device__ __forceinline__ void ldsm4(uint32_t addr, uint32_t& r0, uint32_t& r1,
                                             uint32_t& r2, uint32_t& r3) {
    asm volatile("ldmatrix.sync.aligned.m8n8.x4.shared.b16 {%0,%1,%2,%3}, [%4];"
        : "=r"(r0), "=r"(r1), "=r"(r2), "=r"(r3) : "r"(addr));
}
static __device__ __forceinline__ void ldsm2(uint32_t addr, uint32_t& r0, uint32_t& r1) {
    asm volatile("ldmatrix.sync.aligned.m8n8.x2.shared.b16 {%0,%1}, [%2];"
        : "=r"(r0), "=r"(r1) : "r"(addr));
}
static __device__ __forceinline__ void mma16(float* c, const uint32_t* a, uint32_t b0, uint32_t b1) {
    asm volatile("mma.sync.aligned.m16n8k16.row.col.f32.f16.f16.f32 "
        "{%0,%1,%2,%3},{%4,%5,%6,%7},{%8,%9},{%0,%1,%2,%3};"
        : "+f"(c[0]), "+f"(c[1]), "+f"(c[2]), "+f"(c[3])
        : "r"(a[0]), "r"(a[1]), "r"(a[2]), "r"(a[3]), "r"(b0), "r"(b1));
}
static __device__ __forceinline__ void mma8(float* c, const uint32_t* a, uint32_t b0) {
    asm volatile("mma.sync.aligned.m16n8k8.row.col.f32.f16.f16.f32 "
        "{%0,%1,%2,%3},{%4,%5},{%6},{%0,%1,%2,%3};"
        : "+f"(c[0]), "+f"(c[1]), "+f"(c[2]), "+f"(c[3])
        : "r"(a[0]), "r"(a[1]), "r"(b0));
}

// ---------------- one layer GEMM for this warp (M=16) ----------------
// A rows [m0, m0+16) from Xact (K = 16*KST + 8, tail at k=16*KST).
// W at wbase, row stride WSBI. N in NCH chunks of 64.
// EPI 0: tanh -> Xact.  EPI 1: k-epilogue (tanh * dx, c-reduce -> KB).
template<int KST, int NCH, int EPI, int WSBI>
static __device__ __forceinline__ void gemm_layer(
    char* sm, uint32_t smb, uint32_t wbase, int m0, int lane)
{
    const uint32_t XB = smb + OFF_XACT;
    const int ar = (lane & 7) + ((lane >> 3) & 1) * 8;   // A x4 row offset
    const int ak = ((lane >> 4) & 1) * 8;                // A x4 k offset
    const int br = (lane & 7) + ((lane >> 4) & 1) * 8;   // B x4 row offset
    const int bk = ((lane >> 3) & 1) * 8;                // B x4 k offset
    const int rr = lane & 15;                            // x2 row offset

    // ---- hoist A fragments (before epilogue overwrites Xact in place) ----
    uint32_t AF[KST][4];
    uint32_t AT[2];
#pragma unroll
    for (int ks = 0; ks < KST; ks++)
        ldsm4(XB + (uint32_t)(m0 + ar) * XSB + (uint32_t)(ks * 16 + ak) * 2,
              AF[ks][0], AF[ks][1], AF[ks][2], AF[ks][3]);
    ldsm2(XB + (uint32_t)(m0 + rr) * XSB + (uint32_t)(KST * 16) * 2, AT[0], AT[1]);

    const int g  = lane >> 2;
    const int q2 = (lane & 3) * 2;

#pragma unroll
    for (int ch = 0; ch < NCH; ch++) {
        const int n0 = ch * 64;
        float acc[8][4];
#pragma unroll
        for (int nt = 0; nt < 8; nt++)
#pragma unroll
            for (int j = 0; j < 4; j++) acc[nt][j] = 0.0f;

#pragma unroll
        for (int ks = 0; ks < KST; ks++) {
#pragma unroll
            for (int np = 0; np < 4; np++) {
                uint32_t b0, b1, b2, b3;
                ldsm4(wbase + (uint32_t)(n0 + np * 16 + br) * WSBI + (uint32_t)(ks * 16 + bk) * 2,
                      b0, b1, b2, b3);
                mma16(acc[2 * np],     AF[ks], b0, b1);
                mma16(acc[2 * np + 1], AF[ks], b2, b3);
            }
        }
        { // K tail (k8)
#pragma unroll
            for (int np = 0; np < 4; np++) {
                uint32_t b0, b1;
                ldsm2(wbase + (uint32_t)(n0 + np * 16 + rr) * WSBI + (uint32_t)(KST * 16) * 2,
                      b0, b1);
                mma8(acc[2 * np],     AT, b0);
                mma8(acc[2 * np + 1], AT, b1);
            }
        }

        if (EPI == 0) {
            // tanh -> Xact (fp16) at cols n0..n0+63, rows m0+g / m0+g+8
            int rowA = m0 + g;
#pragma unroll
            for (int nt = 0; nt < 8; nt++) {
                int col = n0 + nt * 8 + q2;
                __half2 lo = __floats2half2_rn(tanh_fast(acc[nt][0]), tanh_fast(acc[nt][1]));
                __half2 hi = __floats2half2_rn(tanh_fast(acc[nt][2]), tanh_fast(acc[nt][3]));
                *(__half2*)(sm + OFF_XACT + (size_t)rowA * XSB + col * 2)       = lo;
                *(__half2*)(sm + OFF_XACT + (size_t)(rowA + 8) * XSB + col * 2) = hi;
            }
        } else {
            // k-epilogue: k[row][h] = sum_c tanh(D)*dx[row][c]
            const float* dxs = (const float*)(sm + OFF_DX);
            float* kb = (float*)(sm + OFF_KB);
            int rA = m0 + g, rB = rA + 8;
            float2 dA = *(const float2*)(dxs + rA * 8 + q2);
            float2 dB = *(const float2*)(dxs + rB * 8 + q2);
#pragma unroll
            for (int nt = 0; nt < 8; nt++) {
                int h = (n0 >> 3) + nt;
                float pA = tanh_fast(acc[nt][0]) * dA.x + tanh_fast(acc[nt][1]) * dA.y;
                float pB = tanh_fast(acc[nt][2]) * dB.x + tanh_fast(acc[nt][3]) * dB.y;
                pA += __shfl_xor_sync(0xFFFFFFFFu, pA, 1);
                pA += __shfl_xor_sync(0xFFFFFFFFu, pA, 2);
                pB += __shfl_xor_sync(0xFFFFFFFFu, pB, 1);
                pB += __shfl_xor_sync(0xFFFFFFFFu, pB, 2);
                if ((lane & 3) == 0) {
                    kb[rA * 33 + h] = pA;
                    kb[rB * 33 + h] = pB;
                }
            }
        }
    }
}

// ---------------- kernel ----------------
__global__ void __launch_bounds__(TPB, 1) cde_kernel(
    const float* __restrict__ coeffs,
    const float* __restrict__ iW1, const float* __restrict__ ib1,
    const float* __restrict__ iW2, const float* __restrict__ ib2,
    const float* __restrict__ fW1, const float* __restrict__ fb1,
    const float* __restrict__ fW2, const float* __restrict__ fb2,
    const float* __restrict__ fW3, const float* __restrict__ fb3,
    const float* __restrict__ rW1, const float* __restrict__ rb1,
    const float* __restrict__ rW2, const float* __restrict__ rb2,
    float* __restrict__ out)
{
    extern __shared__ char sm[];
    const uint32_t smb = smem_u32(sm);
    const int tid  = threadIdx.x;
    const int lane = tid & 31;
    const int m0   = (tid >> 5) * 16;                    // warp's M base (8 warps x 16 rows)
    const bool owner = tid < ROWS;                       // threads 0..127 own a batch row
    const size_t b = (size_t)blockIdx.x * ROWS + tid;    // valid only when owner

    // ========== weight staging: fp16 [N][K] row-major, bias folded at k=K_real ==========
    for (int e = tid; e < 128 * 40; e += TPB) {
        int n = e / 40, k = e % 40;
        float v = (k < 32) ? fW1[k * 128 + n] : (k == 32 ? fb1[n] : 0.0f);
        *(__half*)(sm + OFF_W1 + (size_t)n * W1SB + k * 2) = __float2half_rn(v);
    }
    for (int e = tid; e < 128 * 136; e += TPB) {
        int n = e / 136, k = e % 136;
        float v = (k < 128) ? fW2[k * 128 + n] : (k == 128 ? fb2[n] : 0.0f);
        *(__half*)(sm + OFF_W2 + (size_t)n * WSB + k * 2) = __float2half_rn(v);
    }
    for (int e = tid; e < 256 * 136; e += TPB) {
        int n = e / 136, k = e % 136;
        float v = (k < 128) ? fW3[k * 256 + n] : (k == 128 ? fb3[n] : 0.0f);
        *(__half*)(sm + OFF_W3 + (size_t)n * WSB + k * 2) = __float2half_rn(v);
    }
    {
        float* rw = (float*)(sm + OFF_RW);
        for (int i = tid; i < 1024; i += TPB) rw[RW1 + i] = rW1[i];
        if (tid < 32) { rw[RB1 + tid] = rb1[tid]; rw[RW2 + tid] = rW2[tid]; }
        if (tid == 0) rw[RB2] = rb2[0];
    }

    // ========== z0 = initial(X(0)) (owners only) ==========
    const float* base_c = coeffs + (owner ? b : 0) * (size_t)(127 * 32);
    float z[32];
    __half2* xr = (__half2*)(sm + OFF_XACT + (size_t)(owner ? tid : 0) * XSB);
    if (owner) {
        float X0[8];
        float4 q0 = *(const float4*)(base_c + 0);
        float4 q1 = *(const float4*)(base_c + 4);
        X0[0]=q0.x; X0[1]=q0.y; X0[2]=q0.z; X0[3]=q0.w;
        X0[4]=q1.x; X0[5]=q1.y; X0[6]=q1.z; X0[7]=q1.w;
#pragma unroll
        for (int i = 0; i < 32; i++) z[i] = ib2[i];
        for (int j = 0; j < 64; j++) {
            float hj = ib1[j];
#pragma unroll
            for (int c = 0; c < 8; c++) hj += X0[c] * iW1[c * 64 + j];
            hj = fmaxf(hj, 0.0f);
#pragma unroll
            for (int i = 0; i < 32; i++) z[i] += hj * iW2[j * 32 + i];
        }
        // initial Xact row: arg = z, bias cols
#pragma unroll
        for (int i = 0; i < 16; i++) xr[i] = __floats2half2_rn(z[2 * i], z[2 * i + 1]);
        xr[16] = __floats2half2_rn(1.0f, 0.0f);          // bias col 32 (layer1)
        xr[17] = xr[18] = xr[19] = __floats2half2_rn(0.0f, 0.0f);
        xr[64] = __floats2half2_rn(1.0f, 0.0f);          // bias col 128 (layer2/3)
        xr[65] = xr[66] = xr[67] = __floats2half2_rn(0.0f, 0.0f);
    }
    __syncthreads();   // weights + activations visible CTA-wide

    // ---- knot 0 readout ----
    if (owner) {
        const float* rw = (const float*)(sm + OFF_RW);
        float h[32];
#pragma unroll
        for (int j = 0; j < 32; j++) h[j] = rw[RB1 + j];
#pragma unroll
        for (int i = 0; i < 32; i++) {
            float zi = z[i];
#pragma unroll
            for (int j = 0; j < 32; j++) h[j] += zi * rw[RW1 + i * 32 + j];
        }
        float y = rw[RB2];
#pragma unroll
        for (int j = 0; j < 32; j++) y += fmaxf(h[j], 0.0f) * rw[RW2 + j];
        out[b * 128] = y;
    }

    // ========== RK4 (3/8 rule) main loop ==========
    float* acp = (float*)(sm + OFF_AC) + tid * 33;
    float* dbp = (float*)(sm + OFF_DB) + tid * 33;
    float* kbp = (float*)(sm + OFF_KB) + tid * 33;
    float* dxp = (float*)(sm + OFF_DX) + tid * 8;

    int cur = -1;
    float cb[8], c2r[8], c3r[8];

#pragma unroll 1
    for (int step = 0; step < NSTEPS; step++) {
        const float t0 = 0.5f * (float)step;
#pragma unroll 1
        for (int s = 0; s < 4; s++) {
            // ---- dx(ts) for own row -> smem (owners) ----
            if (owner) {
                float ts = t0 + (s == 0 ? 0.0f : s == 1 ? 0.16666667f
                                               : s == 2 ? 0.33333334f : 0.5f);
                int id = (int)ts; if (id > 126) id = 126;
                float fr = ts - (float)id;
                if (id != cur) {
                    cur = id;
                    const float4* cp = (const float4*)(base_c + (size_t)id * 32);
                    float4 q;
                    q = cp[2]; cb[0]=q.x;  cb[1]=q.y;  cb[2]=q.z;  cb[3]=q.w;
                    q = cp[3]; cb[4]=q.x;  cb[5]=q.y;  cb[6]=q.z;  cb[7]=q.w;
                    q = cp[4]; c2r[0]=q.x; c2r[1]=q.y; c2r[2]=q.z; c2r[3]=q.w;
                    q = cp[5]; c2r[4]=q.x; c2r[5]=q.y; c2r[6]=q.z; c2r[7]=q.w;
                    q = cp[6]; c3r[0]=q.x; c3r[1]=q.y; c3r[2]=q.z; c3r[3]=q.w;
                    q = cp[7]; c3r[4]=q.x; c3r[5]=q.y; c3r[6]=q.z; c3r[7]=q.w;
                }
#pragma unroll
                for (int c = 0; c < 8; c++)
                    dxp[c] = cb[c] + (c2r[c] + c3r[c] * fr) * fr;
            }
            __syncthreads();   // A: dx + previous combine's xr visible to all warps

            // ---- 3-layer MLP (warp-local rows m0..m0+15) ----
            gemm_layer<2, 2, 0, W1SB>(sm, smb, smb + OFF_W1, m0, lane);
            __syncwarp();
            gemm_layer<8, 2, 0, WSB>(sm, smb, smb + OFF_W2, m0, lane);
            __syncwarp();
            gemm_layer<8, 4, 1, WSB>(sm, smb, smb + OFF_W3, m0, lane);
            __syncthreads();   // B: kb visible to the row-owner threads

            // ---- RK4 combination (owner thread = own row), write next arg ----
            if (owner) {
#pragma unroll
                for (int i = 0; i < 32; i += 2) {
                    float k0 = kbp[i], k1 = kbp[i + 1];
                    float v0, v1;
                    if (s == 0) {
                        acp[i] = k0; acp[i + 1] = k1;
                        dbp[i] = k0; dbp[i + 1] = k1;
                        v0 = z[i]     + k0 * (1.0f / 6.0f);
                        v1 = z[i + 1] + k1 * (1.0f / 6.0f);
                    } else if (s == 1) {
                        float a0 = acp[i] + 3.0f * k0, a1 = acp[i + 1] + 3.0f * k1;
                        float d0 = dbp[i] - k0,        d1 = dbp[i + 1] - k1;
                        acp[i] = a0; acp[i + 1] = a1;
                        dbp[i] = d0; dbp[i + 1] = d1;
                        v0 = z[i]     + (a0 - 3.0f * d0) * (1.0f / 12.0f);
                        v1 = z[i + 1] + (a1 - 3.0f * d1) * (1.0f / 12.0f);
                    } else if (s == 2) {
                        float a0 = acp[i] + 3.0f * k0, a1 = acp[i + 1] + 3.0f * k1;
                        float d0 = dbp[i] + k0,        d1 = dbp[i + 1] + k1;
                        acp[i] = a0; acp[i + 1] = a1;
                        dbp[i] = d0; dbp[i + 1] = d1;
                        v0 = z[i]     + 0.5f * d0;
                        v1 = z[i + 1] + 0.5f * d1;
                    } else {
                        z[i]     += 0.0625f * (acp[i]     + k0);
                        z[i + 1] += 0.0625f * (acp[i + 1] + k1);
                        v0 = z[i]; v1 = z[i + 1];
                    }
                    xr[i >> 1] = __floats2half2_rn(v0, v1);
                }
                // restore layer-1 bias/zero cols (clobbered by layer-1 epilogue)
                xr[16] = __floats2half2_rn(1.0f, 0.0f);
                xr[17] = xr[18] = xr[19] = __floats2half2_rn(0.0f, 0.0f);
            }
            // barrier A of next sub-step publishes xr before the next layer-1
        }

        // ---- readout at integer knots ----
        if ((step & 1) && owner) {
            const float* rw = (const float*)(sm + OFF_RW);
            float h[32];
#pragma unroll
            for (int j = 0; j < 32; j++) h[j] = rw[RB1 + j];
#pragma unroll
            for (int i = 0; i < 32; i++) {
                float zi = z[i];
#pragma unroll
                for (int j = 0; j < 32; j++) h[j] += zi * rw[RW1 + i * 32 + j];
            }
            float y = rw[RB2];
#pragma unroll
            for (int j = 0; j < 32; j++) y += fmaxf(h[j], 0.0f) * rw[RW2 + j];
            out[b * 128 + (size_t)((step >> 1) + 1)] = y;
        }
    }
}

extern "C" void kernel_launch(void* const* d_in, const int* in_sizes, int n_in,
                              void* d_out, int out_size)
{
    (void)in_sizes; (void)n_in; (void)out_size;
    cudaFuncSetAttribute(cde_kernel, cudaFuncAttributeMaxDynamicSharedMemorySize, SMEM_TOTAL);
    cde_kernel<<<128, TPB, SMEM_TOTAL>>>(
        (const float*)d_in[0],                              // coeffs (d_in[1]=t_eval unused)
        (const float*)d_in[2],  (const float*)d_in[3],      // iW1, ib1
        (const float*)d_in[4],  (const float*)d_in[5],      // iW2, ib2
        (const float*)d_in[6],  (const float*)d_in[7],      // fW1, fb1
        (const float*)d_in[8],  (const float*)d_in[9],      // fW2, fb2
        (const float*)d_in[10], (const float*)d_in[11],     // fW3, fb3
        (const float*)d_in[12], (const float*)d_in[13],     // rW1, rb1
        (const float*)d_in[14], (const float*)d_in[15],     // rW2, rb2
        (float*)d_out);
}